// round 9
// baseline (speedup 1.0000x reference)
#include <cuda_runtime.h>

// Problem constants
#define BB 16
#define CC 64
#define HH 256
#define WW 256
#define HW (HH*WW)
#define KPOS 9          // 3x3
#define JDIM (CC*KPOS)  // 576

// Scratch (no allocation allowed in kernel_launch)
__device__ float g_avg[BB*CC];          // 1024 channel means

// ---------------------------------------------------------------------------
// Kernel 1: per-(b,c) spatial mean. At DRAM roofline (81% / 6.45 TB/s).
// ---------------------------------------------------------------------------
__global__ void avg_kernel(const float* __restrict__ x) {
    const int bc = blockIdx.x;
    const float4* p = reinterpret_cast<const float4*>(x + (size_t)bc * HW);
    const int t = threadIdx.x;     // 0..255
    float s = 0.f;
    #pragma unroll 8
    for (int i = 0; i < 64; ++i) {
        float4 v = p[i * 256 + t];
        s += (v.x + v.y) + (v.z + v.w);
    }
    __shared__ float red[256];
    red[t] = s;
    __syncthreads();
    #pragma unroll
    for (int off = 128; off > 0; off >>= 1) {
        if (t < off) red[t] += red[t + off];
        __syncthreads();
    }
    if (t == 0) g_avg[bc] = red[0] * (1.0f / (float)HW);
}

// ---------------------------------------------------------------------------
// Kernel 2: depthwise 3x3 conv + conv_bias, fused with (x-y)*fs*x + y.
// Dynamic weights computed PER-WARP, barrier-free: lanes 0..8 of every warp
// redundantly compute sigmoid(avg[b,:].w1[c*9+k,:] + b1[..]) with a fully
// unrolled float4 dot, then broadcast via __shfl_sync. No smem, no
// __syncthreads -> no CTA-start stall, load stream stays front-batched.
// Conv body: PROVEN 79.8us @ 6084 GB/s (R6). 4 cols/thread, fully coalesced
// LDG.128/STG.128, no shuffles in hot loop; halo = 2 scalar LDGs (L1 hits).
// Rolling 3-row x 6-col register window; streaming stores.
// ---------------------------------------------------------------------------
#define TR 32

__device__ __forceinline__ void load_row6(const float* __restrict__ xp,
                                          int g, int col0,
                                          float& l, float4& v, float& r) {
    v = make_float4(0.f, 0.f, 0.f, 0.f);
    l = 0.f; r = 0.f;
    if ((unsigned)g < HH) {
        const float* rowp = xp + (size_t)g * WW;
        v = *reinterpret_cast<const float4*>(rowp + col0);
        if (col0 > 0)         l = __ldg(rowp + col0 - 1);
        if (col0 < WW - 4)    r = __ldg(rowp + col0 + 4);
    }
}

__global__ void __launch_bounds__(256) conv_kernel(
        const float* __restrict__ x,
        const float* __restrict__ w1,
        const float* __restrict__ b1,
        const float* __restrict__ fscale,
        const float* __restrict__ conv_bias,
        float* __restrict__ out) {
    const int bc   = blockIdx.y;          // 0..1023
    const int b    = bc >> 6;
    const int c    = bc & (CC - 1);
    const int row0 = blockIdx.x * TR;
    const int t    = threadIdx.x;         // 0..255
    const int lane = t & 31;
    const int cg   = t & 63;              // cols [4cg, 4cg+3]
    const int rs   = t >> 6;              // row slice 0..3 (8 rows each)
    const int g0   = row0 + rs * 8;
    const int col0 = cg * 4;

    const float* xp = x + (size_t)bc * HW;

    // Issue the first two (long-latency) row loads before the weight dot,
    // so DRAM latency overlaps the weight computation.
    float  al, ar, bl, br;
    float4 av, bv;
    load_row6(xp, g0 - 1, col0, al, av, ar);
    load_row6(xp, g0,     col0, bl, bv, br);

    // Per-warp dynamic weights (lanes 0..8), broadcast via shuffles.
    float wreg = 0.f;
    if (lane < KPOS) {
        const int j = c * KPOS + lane;
        float acc = __ldg(b1 + j);
        const float4* ap4 = reinterpret_cast<const float4*>(g_avg + b * CC);
        const float4* wr4 = reinterpret_cast<const float4*>(w1 + (size_t)j * CC);
        #pragma unroll
        for (int k = 0; k < CC / 4; ++k) {
            const float4 a4 = ap4[k];
            const float4 q4 = __ldg(&wr4[k]);
            acc += a4.x*q4.x + a4.y*q4.y + a4.z*q4.z + a4.w*q4.w;
        }
        wreg = 1.0f / (1.0f + expf(-acc));
    }
    const float w0  = __shfl_sync(0xffffffffu, wreg, 0);
    const float w1v = __shfl_sync(0xffffffffu, wreg, 1);
    const float w2  = __shfl_sync(0xffffffffu, wreg, 2);
    const float w3  = __shfl_sync(0xffffffffu, wreg, 3);
    const float w4  = __shfl_sync(0xffffffffu, wreg, 4);
    const float w5  = __shfl_sync(0xffffffffu, wreg, 5);
    const float w6  = __shfl_sync(0xffffffffu, wreg, 6);
    const float w7  = __shfl_sync(0xffffffffu, wreg, 7);
    const float w8  = __shfl_sync(0xffffffffu, wreg, 8);
    const float cb  = __ldg(conv_bias + c);
    const float fs  = __ldg(fscale + c);

    float* op = out + (size_t)bc * HW + (size_t)g0 * WW + col0;

    #pragma unroll
    for (int r = 0; r < 8; ++r) {
        float  cl, cr;
        float4 cv;
        load_row6(xp, g0 + r + 1, col0, cl, cv, cr);

        float4 o;
        {   // col0
            float y = cb + w0*al   + w1v*av.x + w2*av.y
                         + w3*bl   + w4 *bv.x + w5*bv.y
                         + w6*cl   + w7 *cv.x + w8*cv.y;
            const float xv = bv.x;
            o.x = (xv - y) * fs * xv + y;
        }
        {   // col0+1
            float y = cb + w0*av.x + w1v*av.y + w2*av.z
                         + w3*bv.x + w4 *bv.y + w5*bv.z
                         + w6*cv.x + w7 *cv.y + w8*cv.z;
            const float xv = bv.y;
            o.y = (xv - y) * fs * xv + y;
        }
        {   // col0+2
            float y = cb + w0*av.y + w1v*av.z + w2*av.w
                         + w3*bv.y + w4 *bv.z + w5*bv.w
                         + w6*cv.y + w7 *cv.z + w8*cv.w;
            const float xv = bv.z;
            o.z = (xv - y) * fs * xv + y;
        }
        {   // col0+3
            float y = cb + w0*av.z + w1v*av.w + w2*ar
                         + w3*bv.z + w4 *bv.w + w5*br
                         + w6*cv.z + w7 *cv.w + w8*cr;
            const float xv = bv.w;
            o.w = (xv - y) * fs * xv + y;
        }
        __stcs(reinterpret_cast<float4*>(op + (size_t)r * WW), o);

        al = bl; av = bv; ar = br;
        bl = cl; bv = cv; br = cr;
    }
}

// ---------------------------------------------------------------------------
// Launch: x, w1, b1, fscale, conv_bias (metadata order); out fp32.
// ---------------------------------------------------------------------------
extern "C" void kernel_launch(void* const* d_in, const int* in_sizes, int n_in,
                              void* d_out, int out_size) {
    const float* x         = (const float*)d_in[0];
    const float* w1        = (const float*)d_in[1];
    const float* b1        = (const float*)d_in[2];
    const float* fscale    = (const float*)d_in[3];
    const float* conv_bias = (const float*)d_in[4];
    float* out = (float*)d_out;

    avg_kernel<<<BB * CC, 256>>>(x);
    conv_kernel<<<dim3(HH / TR, BB * CC), 256>>>(x, w1, b1, fscale, conv_bias, out);
}

// round 12
// speedup vs baseline: 1.1647x; 1.1647x over previous
#include <cuda_runtime.h>

// Problem constants
#define BB 16
#define CC 64
#define HH 256
#define WW 256
#define HW (HH*WW)
#define KPOS 9          // 3x3
#define JDIM (CC*KPOS)  // 576

// Scratch (no allocation allowed in kernel_launch)
__device__ __align__(16) float g_avg[BB*CC];   // 1024 channel means

// ---------------------------------------------------------------------------
// Kernel 1: per-(b,c) spatial mean. At DRAM roofline (81% / 6.45 TB/s).
// ---------------------------------------------------------------------------
__global__ void avg_kernel(const float* __restrict__ x) {
    const int bc = blockIdx.x;
    const float4* p = reinterpret_cast<const float4*>(x + (size_t)bc * HW);
    const int t = threadIdx.x;     // 0..255
    float s = 0.f;
    #pragma unroll 8
    for (int i = 0; i < 64; ++i) {
        float4 v = p[i * 256 + t];
        s += (v.x + v.y) + (v.z + v.w);
    }
    __shared__ float red[256];
    red[t] = s;
    __syncthreads();
    #pragma unroll
    for (int off = 128; off > 0; off >>= 1) {
        if (t < off) red[t] += red[t + off];
        __syncthreads();
    }
    if (t == 0) g_avg[bc] = red[0] * (1.0f / (float)HW);
}

// ---------------------------------------------------------------------------
// Kernel 2: depthwise 3x3 conv + conv_bias, fused with (x-y)*fs*x + y.
// Inline dynamic weights with SHORT critical path, WARP-SAFE: warps 0..4
// (t<160) all participate; widx = min(t>>4, 8) so lanes 144..159 duplicate
// the widx=8 group (same value, benign). One float4 FMA per thread, 4-step
// 16-lane shfl reduce, sigmoid, smem, one __syncthreads.
// (R11 hang root-cause: full-mask shfl inside `t<144` split warp 4.)
// Conv body: PROVEN 79.8us @ 6084 GB/s (R6). 4 cols/thread, fully coalesced
// LDG.128/STG.128, no shuffles in hot loop; halo = 2 scalar LDGs (L1 hits).
// Rolling 3-row x 6-col register window; streaming stores.
// ---------------------------------------------------------------------------
#define TR 32

__device__ __forceinline__ void load_row6(const float* __restrict__ xp,
                                          int g, int col0,
                                          float& l, float4& v, float& r) {
    v = make_float4(0.f, 0.f, 0.f, 0.f);
    l = 0.f; r = 0.f;
    if ((unsigned)g < HH) {
        const float* rowp = xp + (size_t)g * WW;
        v = *reinterpret_cast<const float4*>(rowp + col0);
        if (col0 > 0)         l = __ldg(rowp + col0 - 1);
        if (col0 < WW - 4)    r = __ldg(rowp + col0 + 4);
    }
}

__global__ void __launch_bounds__(256) conv_kernel(
        const float* __restrict__ x,
        const float* __restrict__ w1,
        const float* __restrict__ b1,
        const float* __restrict__ fscale,
        const float* __restrict__ conv_bias,
        float* __restrict__ out) {
    const int bc   = blockIdx.y;          // 0..1023
    const int b    = bc >> 6;
    const int c    = bc & (CC - 1);
    const int row0 = blockIdx.x * TR;
    const int t    = threadIdx.x;         // 0..255
    const int cg   = t & 63;              // cols [4cg, 4cg+3]
    const int rs   = t >> 6;              // row slice 0..3 (8 rows each)
    const int g0   = row0 + rs * 8;
    const int col0 = cg * 4;

    const float* xp = x + (size_t)bc * HW;

    // Issue the first two (long-latency) row loads before the weight work.
    float  al, ar, bl, br;
    float4 av, bv;
    load_row6(xp, g0 - 1, col0, al, av, ar);
    load_row6(xp, g0,     col0, bl, bv, br);

    // Distributed inline weights over whole warps 0..4 (t < 160).
    __shared__ float wsh[KPOS];
    if (t < 160) {                        // warps 0..4, all 32 lanes active
        int widx = t >> 4;                // 0..9
        if (widx > 8) widx = 8;           // lanes 144..159 duplicate widx=8
        const int seg = t & 15;           // 0..15 (4 channels each)
        const int j   = c * KPOS + widx;
        const float4 a4 = reinterpret_cast<const float4*>(g_avg + b * CC)[seg];
        const float4 q4 = __ldg(reinterpret_cast<const float4*>(
                                    w1 + (size_t)j * CC) + seg);
        float acc = a4.x*q4.x + a4.y*q4.y + a4.z*q4.z + a4.w*q4.w;
        acc += __shfl_down_sync(0xffffffffu, acc, 8, 16);
        acc += __shfl_down_sync(0xffffffffu, acc, 4, 16);
        acc += __shfl_down_sync(0xffffffffu, acc, 2, 16);
        acc += __shfl_down_sync(0xffffffffu, acc, 1, 16);
        if (seg == 0)                     // t=144 rewrites wsh[8] (same value)
            wsh[widx] = 1.0f / (1.0f + expf(-(acc + __ldg(b1 + j))));
    }
    __syncthreads();

    const float w0 = wsh[0], w1v = wsh[1], w2 = wsh[2];
    const float w3 = wsh[3], w4  = wsh[4], w5 = wsh[5];
    const float w6 = wsh[6], w7  = wsh[7], w8 = wsh[8];
    const float cb = __ldg(conv_bias + c);
    const float fs = __ldg(fscale + c);

    float* op = out + (size_t)bc * HW + (size_t)g0 * WW + col0;

    #pragma unroll
    for (int r = 0; r < 8; ++r) {
        float  cl, cr;
        float4 cv;
        load_row6(xp, g0 + r + 1, col0, cl, cv, cr);

        float4 o;
        {   // col0
            float y = cb + w0*al   + w1v*av.x + w2*av.y
                         + w3*bl   + w4 *bv.x + w5*bv.y
                         + w6*cl   + w7 *cv.x + w8*cv.y;
            const float xv = bv.x;
            o.x = (xv - y) * fs * xv + y;
        }
        {   // col0+1
            float y = cb + w0*av.x + w1v*av.y + w2*av.z
                         + w3*bv.x + w4 *bv.y + w5*bv.z
                         + w6*cv.x + w7 *cv.y + w8*cv.z;
            const float xv = bv.y;
            o.y = (xv - y) * fs * xv + y;
        }
        {   // col0+2
            float y = cb + w0*av.y + w1v*av.z + w2*av.w
                         + w3*bv.y + w4 *bv.z + w5*bv.w
                         + w6*cv.y + w7 *cv.z + w8*cv.w;
            const float xv = bv.z;
            o.z = (xv - y) * fs * xv + y;
        }
        {   // col0+3
            float y = cb + w0*av.z + w1v*av.w + w2*ar
                         + w3*bv.z + w4 *bv.w + w5*br
                         + w6*cv.z + w7 *cv.w + w8*cr;
            const float xv = bv.w;
            o.w = (xv - y) * fs * xv + y;
        }
        __stcs(reinterpret_cast<float4*>(op + (size_t)r * WW), o);

        al = bl; av = bv; ar = br;
        bl = cl; bv = cv; br = cr;
    }
}

// ---------------------------------------------------------------------------
// Launch: x, w1, b1, fscale, conv_bias (metadata order); out fp32.
// ---------------------------------------------------------------------------
extern "C" void kernel_launch(void* const* d_in, const int* in_sizes, int n_in,
                              void* d_out, int out_size) {
    const float* x         = (const float*)d_in[0];
    const float* w1        = (const float*)d_in[1];
    const float* b1        = (const float*)d_in[2];
    const float* fscale    = (const float*)d_in[3];
    const float* conv_bias = (const float*)d_in[4];
    float* out = (float*)d_out;

    avg_kernel<<<BB * CC, 256>>>(x);
    conv_kernel<<<dim3(HH / TR, BB * CC), 256>>>(x, w1, b1, fscale, conv_bias, out);
}